// round 3
// baseline (speedup 1.0000x reference)
#include <cuda_runtime.h>
#include <math.h>

// Problem constants (fixed shapes for this problem instance)
#define Zc 512
#define Hc 256
#define NMAX 20000
#define BMAX 32
#define DPB 32     // docs per block in doc kernel (8 per thread)
#define SDOCS 8    // docs per block in score kernel
#define KMAX 8
#define SEG 20     // top-k stage-1 segments per query
#define SEGMAX 32

// Scratch (no allocations allowed anywhere)
__device__ float g_qb[BMAX * Hc];                 // qa + b1, [B,H]
__device__ float g_da[(size_t)NMAX * Hc];         // d_t @ W1[H:], [N,H]
__device__ float g_scores[(size_t)BMAX * NMAX];   // scaled scores [B,N]
__device__ unsigned long long g_part[BMAX * SEGMAX * KMAX]; // stage-1 top-8 keys

__device__ __forceinline__ float gelu_f(float x) {
    // exact gelu: 0.5*x*(1+erf(x/sqrt(2)))
    return 0.5f * x * (1.0f + erff(x * 0.70710678118654752440f));
}

// ---------------------------------------------------------------------------
// Kernel 1: query path.  grid = B, block = 256 (one thread per h)
// ---------------------------------------------------------------------------
__global__ __launch_bounds__(256) void query_kernel(
    const float* __restrict__ q, const float* __restrict__ Wq,
    const float* __restrict__ bq, const float* __restrict__ lnw,
    const float* __restrict__ lnb, const float* __restrict__ W1,
    const float* __restrict__ b1)
{
    __shared__ float xq[Zc];
    __shared__ float qt[Hc];
    __shared__ float red[18];
    int b = blockIdx.x, t = threadIdx.x;
    const float* row = q + (size_t)b * Zc;
    for (int i = t; i < Zc; i += 256) xq[i] = row[i];
    __syncthreads();

    float acc = bq[t];
    #pragma unroll 8
    for (int z = 0; z < Zc; z++) acc = fmaf(xq[z], Wq[z * Hc + t], acc);
    float g = gelu_f(acc);

    float s = g, s2 = g * g;
    #pragma unroll
    for (int o = 16; o; o >>= 1) {
        s  += __shfl_down_sync(0xffffffffu, s, o);
        s2 += __shfl_down_sync(0xffffffffu, s2, o);
    }
    if ((t & 31) == 0) { red[t >> 5] = s; red[8 + (t >> 5)] = s2; }
    __syncthreads();
    if (t == 0) {
        float S = 0.f, S2 = 0.f;
        for (int w = 0; w < 8; w++) { S += red[w]; S2 += red[8 + w]; }
        float mu = S / (float)Hc;
        red[16] = mu;
        red[17] = S2 / (float)Hc - mu * mu;
    }
    __syncthreads();
    float mu = red[16], var = red[17];
    float v = (g - mu) * rsqrtf(var + 1e-5f) * lnw[t] + lnb[t];
    qt[t] = v;
    __syncthreads();

    float a2 = b1[t];  // fold b1 here
    #pragma unroll 8
    for (int j = 0; j < Hc; j++) a2 = fmaf(qt[j], W1[j * Hc + t], a2);
    g_qb[b * Hc + t] = a2;
}

// ---------------------------------------------------------------------------
// Kernel 2: doc path, fused.  grid = ceil(N/DPB), block = 256.
// hg = tid&63 owns h = 4*hg..4*hg+3 (float4); ds = tid>>6 owns 8 docs
// {ds, ds+4, ..., ds+28}. Doc rows read straight from global (warp-uniform
// broadcast loads, L1-resident); d_t lives only in smem; only da is written.
// ---------------------------------------------------------------------------
__global__ __launch_bounds__(256) void doc_kernel(
    const float* __restrict__ docs, const float* __restrict__ Wd,
    const float* __restrict__ bd, const float* __restrict__ lnw,
    const float* __restrict__ lnb, const float* __restrict__ W1, int N)
{
    __shared__ float dt[DPB][Hc];   // 32 KB
    int t = threadIdx.x;
    int hg = t & 63, ds = t >> 6;
    int h4 = hg * 4;
    int docBase = blockIdx.x * DPB;

    const float4* xp[8];
    #pragma unroll
    for (int i = 0; i < 8; i++) {
        int d = docBase + ds + 4 * i;
        if (d >= N) d = N - 1;
        xp[i] = (const float4*)(docs + (size_t)d * Zc);
    }

    // GEMM1: d = x @ Wd + bd  (each thread: 4h x 8docs)
    float4 bd4 = *(const float4*)&bd[h4];
    float4 acc[8];
    #pragma unroll
    for (int i = 0; i < 8; i++) acc[i] = bd4;

    const float4* wp = (const float4*)(Wd + h4);   // row stride = Hc/4 float4
    for (int z4 = 0; z4 < Zc / 4; z4++) {
        float xv[8][4];
        #pragma unroll
        for (int i = 0; i < 8; i++) {
            float4 x = xp[i][z4];
            xv[i][0] = x.x; xv[i][1] = x.y; xv[i][2] = x.z; xv[i][3] = x.w;
        }
        #pragma unroll
        for (int u = 0; u < 4; u++) {
            float4 w = wp[(z4 * 4 + u) * (Hc / 4)];
            #pragma unroll
            for (int i = 0; i < 8; i++) {
                acc[i].x = fmaf(w.x, xv[i][u], acc[i].x);
                acc[i].y = fmaf(w.y, xv[i][u], acc[i].y);
                acc[i].z = fmaf(w.z, xv[i][u], acc[i].z);
                acc[i].w = fmaf(w.w, xv[i][u], acc[i].w);
            }
        }
    }
    #pragma unroll
    for (int i = 0; i < 8; i++) {
        dt[ds + 4 * i][h4 + 0] = gelu_f(acc[i].x);
        dt[ds + 4 * i][h4 + 1] = gelu_f(acc[i].y);
        dt[ds + 4 * i][h4 + 2] = gelu_f(acc[i].z);
        dt[ds + 4 * i][h4 + 3] = gelu_f(acc[i].w);
    }
    __syncthreads();

    // LayerNorm per doc: warp wid normalizes docs 4*wid .. 4*wid+3
    {
        int wid = t >> 5, lane = t & 31;
        #pragma unroll
        for (int dd = 0; dd < 4; dd++) {
            float* r = dt[wid * 4 + dd];
            float s = 0.f, s2 = 0.f;
            #pragma unroll
            for (int j = lane; j < Hc; j += 32) { float v = r[j]; s += v; s2 += v * v; }
            #pragma unroll
            for (int o = 16; o; o >>= 1) {
                s  += __shfl_xor_sync(0xffffffffu, s, o);
                s2 += __shfl_xor_sync(0xffffffffu, s2, o);
            }
            float mu = s / (float)Hc;
            float rin = rsqrtf(s2 / (float)Hc - mu * mu + 1e-5f);
            #pragma unroll
            for (int j = lane; j < Hc; j += 32)
                r[j] = (r[j] - mu) * rin * lnw[j] + lnb[j];
        }
    }
    __syncthreads();

    // GEMM2: da = dt @ W1[H:2H]
    float4 c[8];
    #pragma unroll
    for (int i = 0; i < 8; i++) c[i] = make_float4(0.f, 0.f, 0.f, 0.f);
    const float4* w1p = (const float4*)(W1 + (size_t)Hc * Hc + h4);
    for (int j4 = 0; j4 < Hc / 4; j4++) {
        float xv[8][4];
        #pragma unroll
        for (int i = 0; i < 8; i++) {
            float4 x = *(const float4*)&dt[ds + 4 * i][j4 * 4];
            xv[i][0] = x.x; xv[i][1] = x.y; xv[i][2] = x.z; xv[i][3] = x.w;
        }
        #pragma unroll
        for (int u = 0; u < 4; u++) {
            float4 w = w1p[(j4 * 4 + u) * (Hc / 4)];
            #pragma unroll
            for (int i = 0; i < 8; i++) {
                c[i].x = fmaf(w.x, xv[i][u], c[i].x);
                c[i].y = fmaf(w.y, xv[i][u], c[i].y);
                c[i].z = fmaf(w.z, xv[i][u], c[i].z);
                c[i].w = fmaf(w.w, xv[i][u], c[i].w);
            }
        }
    }
    #pragma unroll
    for (int i = 0; i < 8; i++) {
        int d = docBase + ds + 4 * i;
        if (d < N) ((float4*)&g_da[(size_t)d * Hc])[hg] = c[i];
    }
}

// ---------------------------------------------------------------------------
// Kernel 3: pairwise scoring.  grid = N/SDOCS, block = 256.
// d-outer / b-inner: dv hoisted once per doc, 4 independent accumulator
// chains per warp for ILP through erff.
// ---------------------------------------------------------------------------
__global__ __launch_bounds__(256) void score_kernel(
    const float* __restrict__ W2, const float* __restrict__ b2,
    const float* __restrict__ temp, int N)
{
    __shared__ float qbs[BMAX * Hc];   // 32 KB
    __shared__ float das[SDOCS][Hc];   // 8 KB
    __shared__ float w2s[Hc];
    int t = threadIdx.x;

    const float4* qsrc = (const float4*)g_qb;
    float4* qdst = (float4*)qbs;
    #pragma unroll
    for (int i = t; i < BMAX * Hc / 4; i += 256) qdst[i] = qsrc[i];
    w2s[t] = W2[t];
    int docBase = blockIdx.x * SDOCS;
    {
        const float4* dsrc = (const float4*)(g_da + (size_t)docBase * Hc);
        float4* ddst = (float4*)&das[0][0];
        ddst[t] = dsrc[t];
        ddst[t + 256] = dsrc[t + 256];
    }
    __syncthreads();

    float invt = 1.0f / (fabsf(temp[0]) + 1e-8f);
    float bb = b2[0];
    int w = t >> 5, lane = t & 31;

    float wv[8];
    #pragma unroll
    for (int j = 0; j < 8; j++) wv[j] = w2s[lane + 32 * j];

    float qv[4][8];
    #pragma unroll
    for (int bi = 0; bi < 4; bi++) {
        const float* qrow = &qbs[(w + 8 * bi) * Hc];
        #pragma unroll
        for (int j = 0; j < 8; j++) qv[bi][j] = qrow[lane + 32 * j];
    }

    #pragma unroll
    for (int d = 0; d < SDOCS; d++) {
        float dv[8];
        #pragma unroll
        for (int j = 0; j < 8; j++) dv[j] = das[d][lane + 32 * j];
        float acc0 = 0.f, acc1 = 0.f, acc2 = 0.f, acc3 = 0.f;
        #pragma unroll
        for (int j = 0; j < 8; j++) {
            float wj = wv[j], dj = dv[j];
            acc0 = fmaf(gelu_f(qv[0][j] + dj), wj, acc0);
            acc1 = fmaf(gelu_f(qv[1][j] + dj), wj, acc1);
            acc2 = fmaf(gelu_f(qv[2][j] + dj), wj, acc2);
            acc3 = fmaf(gelu_f(qv[3][j] + dj), wj, acc3);
        }
        #pragma unroll
        for (int o = 16; o; o >>= 1) {
            acc0 += __shfl_down_sync(0xffffffffu, acc0, o);
            acc1 += __shfl_down_sync(0xffffffffu, acc1, o);
            acc2 += __shfl_down_sync(0xffffffffu, acc2, o);
            acc3 += __shfl_down_sync(0xffffffffu, acc3, o);
        }
        if (lane == 0) {
            g_scores[(size_t)(w +  0) * N + docBase + d] = (acc0 + bb) * invt;
            g_scores[(size_t)(w +  8) * N + docBase + d] = (acc1 + bb) * invt;
            g_scores[(size_t)(w + 16) * N + docBase + d] = (acc2 + bb) * invt;
            g_scores[(size_t)(w + 24) * N + docBase + d] = (acc3 + bb) * invt;
        }
    }
}

// ---------------------------------------------------------------------------
// Top-k keys: (score, index) packed into one orderable uint64.
// Tie-break: equal score -> smaller index (low word = ~index).
// ---------------------------------------------------------------------------
__device__ __forceinline__ unsigned long long pack_key(float s, int i) {
    unsigned int u = __float_as_uint(s);
    u = (u & 0x80000000u) ? ~u : (u | 0x80000000u);
    return ((unsigned long long)u << 32) | (unsigned int)(~(unsigned int)i);
}

// ---------------------------------------------------------------------------
// Kernel 4a: per-segment top-8.  grid = (SEG, B), block = 128.
// ---------------------------------------------------------------------------
__global__ __launch_bounds__(128) void topk_stage1(int N)
{
    __shared__ unsigned long long sk[128 * KMAX];  // 8 KB
    __shared__ unsigned long long warpmax[4];
    __shared__ unsigned long long bestsh;

    int seg = blockIdx.x, b = blockIdx.y, t = threadIdx.x;
    int nseg = gridDim.x;
    int seglen = (N + nseg - 1) / nseg;
    int start = seg * seglen;
    int end = start + seglen; if (end > N) end = N;

    unsigned long long loc[KMAX];
    #pragma unroll
    for (int j = 0; j < KMAX; j++) loc[j] = 0ull;

    const float* row = g_scores + (size_t)b * N;
    for (int i = start + t; i < end; i += 128) {
        unsigned long long key = pack_key(row[i], i);
        if (key > loc[KMAX - 1]) {
            #pragma unroll
            for (int j = 0; j < KMAX; j++) {
                unsigned long long cur = loc[j];
                bool gt = key > cur;
                loc[j] = gt ? key : cur;
                key    = gt ? cur : key;
            }
        }
    }
    #pragma unroll
    for (int j = 0; j < KMAX; j++) sk[t * KMAX + j] = loc[j];
    __syncthreads();

    int wlane = t & 31, wid = t >> 5;
    for (int r = 0; r < KMAX; r++) {
        unsigned long long m = 0ull;
        #pragma unroll
        for (int j = 0; j < KMAX; j++) {
            unsigned long long v = sk[t * KMAX + j];
            m = (v > m) ? v : m;
        }
        #pragma unroll
        for (int o = 16; o; o >>= 1) {
            unsigned long long v = __shfl_xor_sync(0xffffffffu, m, o);
            m = (v > m) ? v : m;
        }
        if (wlane == 0) warpmax[wid] = m;
        __syncthreads();
        if (t == 0) {
            unsigned long long best = 0ull;
            #pragma unroll
            for (int ww = 0; ww < 4; ww++)
                best = (warpmax[ww] > best) ? warpmax[ww] : best;
            bestsh = best;
            g_part[(b * SEGMAX + seg) * KMAX + r] = best;
        }
        __syncthreads();
        unsigned long long best = bestsh;
        #pragma unroll
        for (int j = 0; j < KMAX; j++)
            if (sk[t * KMAX + j] == best) sk[t * KMAX + j] = 0ull;
        __syncthreads();
    }
}

// ---------------------------------------------------------------------------
// Kernel 4b: merge SEG*8 candidates, softmax, write output.  grid = B.
// ---------------------------------------------------------------------------
__global__ __launch_bounds__(256) void topk_stage2(
    const int* __restrict__ kptr, float* __restrict__ out, int N, int B, int nseg)
{
    __shared__ unsigned long long warpmax[8];
    __shared__ unsigned long long bestsh;

    int b = blockIdx.x, t = threadIdx.x;
    int k = *kptr; if (k > KMAX) k = KMAX; if (k < 1) k = 1;
    int tot = nseg * KMAX;  // <= 256

    unsigned long long my = 0ull;
    if (t < tot) my = g_part[b * SEGMAX * KMAX + t];

    unsigned long long keys[KMAX];
    int wlane = t & 31, wid = t >> 5;
    for (int r = 0; r < k; r++) {
        unsigned long long m = my;
        #pragma unroll
        for (int o = 16; o; o >>= 1) {
            unsigned long long v = __shfl_xor_sync(0xffffffffu, m, o);
            m = (v > m) ? v : m;
        }
        if (wlane == 0) warpmax[wid] = m;
        __syncthreads();
        if (t == 0) {
            unsigned long long best = 0ull;
            #pragma unroll
            for (int ww = 0; ww < 8; ww++)
                best = (warpmax[ww] > best) ? warpmax[ww] : best;
            bestsh = best;
        }
        __syncthreads();
        unsigned long long best = bestsh;
        if (t == 0) keys[r] = best;
        if (my == best) my = 0ull;
        __syncthreads();
    }

    if (t == 0) {
        float gv[KMAX]; int gi[KMAX];
        for (int r = 0; r < k; r++) {
            unsigned int hi = (unsigned int)(keys[r] >> 32);
            unsigned int u = (hi & 0x80000000u) ? (hi ^ 0x80000000u) : ~hi;
            gv[r] = __uint_as_float(u);
            gi[r] = (int)(~(unsigned int)(keys[r] & 0xffffffffu));
        }
        float mx = gv[0], sum = 0.f, ex[KMAX];
        for (int j = 0; j < k; j++) { ex[j] = expf(gv[j] - mx); sum += ex[j]; }
        float inv = 1.0f / sum;
        for (int j = 0; j < k; j++) {
            out[b * k + j] = (float)gi[j];            // top_idx (as float)
            out[B * k + b * k + j] = ex[j] * inv;     // probs
        }
    }
}

// ---------------------------------------------------------------------------
extern "C" void kernel_launch(void* const* d_in, const int* in_sizes, int n_in,
                              void* d_out, int out_size)
{
    const float* query = (const float*)d_in[0];
    const float* docs  = (const float*)d_in[1];
    const int*   kptr  = (const int*)d_in[2];
    const float* Wq    = (const float*)d_in[3];
    const float* bq    = (const float*)d_in[4];
    const float* lnqw  = (const float*)d_in[5];
    const float* lnqb  = (const float*)d_in[6];
    const float* Wd    = (const float*)d_in[7];
    const float* bd    = (const float*)d_in[8];
    const float* lndw  = (const float*)d_in[9];
    const float* lndb  = (const float*)d_in[10];
    const float* W1    = (const float*)d_in[11];
    const float* b1    = (const float*)d_in[12];
    const float* W2    = (const float*)d_in[13];
    const float* b2    = (const float*)d_in[14];
    const float* temp  = (const float*)d_in[15];

    int H = in_sizes[4];            // 256
    int Z = in_sizes[3] / H;        // 512
    int B = in_sizes[0] / Z;        // 32
    int N = in_sizes[1] / Z;        // 20000

    query_kernel<<<B, 256>>>(query, Wq, bq, lnqw, lnqb, W1, b1);
    doc_kernel<<<(N + DPB - 1) / DPB, 256>>>(docs, Wd, bd, lndw, lndb, W1, N);
    score_kernel<<<N / SDOCS, 256>>>(W2, b2, temp, N);
    dim3 g1(SEG, B);
    topk_stage1<<<g1, 128>>>(N);
    topk_stage2<<<B, 256>>>(kptr, (float*)d_out, N, B, SEG);
}

// round 6
// speedup vs baseline: 1.2495x; 1.2495x over previous
#include <cuda_runtime.h>
#include <math.h>

// Problem constants (fixed shapes for this problem instance)
#define Zc 512
#define Hc 256
#define NMAX 20000
#define BMAX 32
#define DPB 16     // docs per block in doc kernel (4 per thread)
#define SDOCS 8    // docs per block in score kernel
#define KMAX 8
#define SEG 8      // top-k stage-1 segments per query (x4 warps = 256 candidates)

// Scratch (no allocations allowed anywhere)
__device__ float g_qb[BMAX * Hc];                 // qa + b1, [B,H]
__device__ float g_da[(size_t)NMAX * Hc];         // d_t @ W1[H:], [N,H]
__device__ float g_scores[(size_t)BMAX * NMAX];   // scaled scores [B,N]
__device__ unsigned long long g_part[BMAX * SEG * 4 * KMAX]; // stage-1 keys

typedef unsigned long long u64;

__device__ __forceinline__ u64 pk2(float a, float b) {
    u64 r; asm("mov.b64 %0, {%1,%2};" : "=l"(r) : "f"(a), "f"(b)); return r;
}
__device__ __forceinline__ void fma2(u64 &d, u64 a, u64 b) {
    asm("fma.rn.f32x2 %0, %1, %2, %0;" : "+l"(d) : "l"(a), "l"(b));
}
__device__ __forceinline__ float2 up2(u64 v) {
    float lo, hi; asm("mov.b64 {%0,%1}, %2;" : "=f"(lo), "=f"(hi) : "l"(v));
    return make_float2(lo, hi);
}

__device__ __forceinline__ float gelu_f(float x) {
    // exact gelu: 0.5*x*(1+erf(x/sqrt(2)))
    return 0.5f * x * (1.0f + erff(x * 0.70710678118654752440f));
}

// ---------------------------------------------------------------------------
// Kernel 1: query path.  grid = B, block = 256 (one thread per h)
// ---------------------------------------------------------------------------
__global__ __launch_bounds__(256) void query_kernel(
    const float* __restrict__ q, const float* __restrict__ Wq,
    const float* __restrict__ bq, const float* __restrict__ lnw,
    const float* __restrict__ lnb, const float* __restrict__ W1,
    const float* __restrict__ b1)
{
    __shared__ float xq[Zc];
    __shared__ float qt[Hc];
    __shared__ float red[18];
    int b = blockIdx.x, t = threadIdx.x;
    const float* row = q + (size_t)b * Zc;
    for (int i = t; i < Zc; i += 256) xq[i] = row[i];
    __syncthreads();

    float acc = bq[t];
    #pragma unroll 8
    for (int z = 0; z < Zc; z++) acc = fmaf(xq[z], Wq[z * Hc + t], acc);
    float g = gelu_f(acc);

    float s = g, s2 = g * g;
    #pragma unroll
    for (int o = 16; o; o >>= 1) {
        s  += __shfl_down_sync(0xffffffffu, s, o);
        s2 += __shfl_down_sync(0xffffffffu, s2, o);
    }
    if ((t & 31) == 0) { red[t >> 5] = s; red[8 + (t >> 5)] = s2; }
    __syncthreads();
    if (t == 0) {
        float S = 0.f, S2 = 0.f;
        for (int w = 0; w < 8; w++) { S += red[w]; S2 += red[8 + w]; }
        float mu = S / (float)Hc;
        red[16] = mu;
        red[17] = S2 / (float)Hc - mu * mu;
    }
    __syncthreads();
    float mu = red[16], var = red[17];
    float v = (g - mu) * rsqrtf(var + 1e-5f) * lnw[t] + lnb[t];
    qt[t] = v;
    __syncthreads();

    float a2 = b1[t];  // fold b1 here
    #pragma unroll 8
    for (int j = 0; j < Hc; j++) a2 = fmaf(qt[j], W1[j * Hc + t], a2);
    g_qb[b * Hc + t] = a2;
}

// ---------------------------------------------------------------------------
// Kernel 2: doc path, fused. grid = N/DPB, block = 256.  (R2 structure,
// GEMM inner loops converted to packed fma.rn.f32x2 — numerically identical
// to two fmaf, half the FMA-pipe instruction count.)
// hg = tid&63 owns h = 4*hg..4*hg+3; ds = tid>>6 owns docs {ds,ds+4,ds+8,ds+12}.
// ---------------------------------------------------------------------------
__global__ __launch_bounds__(256) void doc_kernel(
    const float* __restrict__ docs, const float* __restrict__ Wd,
    const float* __restrict__ bd, const float* __restrict__ lnw,
    const float* __restrict__ lnb, const float* __restrict__ W1, int N)
{
    __shared__ float xs[DPB][Zc];   // 32 KB: raw doc rows
    __shared__ float dt[DPB][Hc];   // 16 KB: activations
    int t = threadIdx.x;
    int hg = t & 63, ds = t >> 6;
    int h4 = hg * 4;
    int docBase = blockIdx.x * DPB;

    const float4* src = (const float4*)(docs + (size_t)docBase * Zc);
    float4* dstp = (float4*)&xs[0][0];
    #pragma unroll
    for (int i = t; i < DPB * Zc / 4; i += 256) dstp[i] = src[i];
    __syncthreads();

    // GEMM1: d = x @ Wd + bd  (each thread: 4h x 4docs, packed f32x2 over h)
    float4 bd4 = *(const float4*)&bd[h4];
    u64 aA[4], aB[4];
    {
        u64 bdA = pk2(bd4.x, bd4.y), bdB = pk2(bd4.z, bd4.w);
        #pragma unroll
        for (int i = 0; i < 4; i++) { aA[i] = bdA; aB[i] = bdB; }
    }
    for (int z4 = 0; z4 < Zc / 4; z4++) {
        float4 x0 = *(const float4*)&xs[ds][z4 * 4];
        float4 x1 = *(const float4*)&xs[ds + 4][z4 * 4];
        float4 x2 = *(const float4*)&xs[ds + 8][z4 * 4];
        float4 x3 = *(const float4*)&xs[ds + 12][z4 * 4];
        float xv[4][4] = {{x0.x, x0.y, x0.z, x0.w}, {x1.x, x1.y, x1.z, x1.w},
                          {x2.x, x2.y, x2.z, x2.w}, {x3.x, x3.y, x3.z, x3.w}};
        #pragma unroll
        for (int u = 0; u < 4; u++) {
            float4 w = *(const float4*)&Wd[(size_t)(z4 * 4 + u) * Hc + h4];
            u64 wA = pk2(w.x, w.y), wB = pk2(w.z, w.w);
            #pragma unroll
            for (int i = 0; i < 4; i++) {
                u64 xx = pk2(xv[i][u], xv[i][u]);
                fma2(aA[i], wA, xx);
                fma2(aB[i], wB, xx);
            }
        }
    }
    #pragma unroll
    for (int i = 0; i < 4; i++) {
        float2 pA = up2(aA[i]), pB = up2(aB[i]);
        dt[ds + 4 * i][h4 + 0] = gelu_f(pA.x);
        dt[ds + 4 * i][h4 + 1] = gelu_f(pA.y);
        dt[ds + 4 * i][h4 + 2] = gelu_f(pB.x);
        dt[ds + 4 * i][h4 + 3] = gelu_f(pB.y);
    }
    __syncthreads();

    // LayerNorm per doc: warp w normalizes docs 2w, 2w+1
    {
        int wid = t >> 5, lane = t & 31;
        #pragma unroll
        for (int dd = 0; dd < 2; dd++) {
            float* r = dt[wid * 2 + dd];
            float s = 0.f, s2 = 0.f;
            #pragma unroll
            for (int j = lane; j < Hc; j += 32) { float v = r[j]; s += v; s2 += v * v; }
            #pragma unroll
            for (int o = 16; o; o >>= 1) {
                s  += __shfl_xor_sync(0xffffffffu, s, o);
                s2 += __shfl_xor_sync(0xffffffffu, s2, o);
            }
            float mu = s / (float)Hc;
            float rin = rsqrtf(s2 / (float)Hc - mu * mu + 1e-5f);
            #pragma unroll
            for (int j = lane; j < Hc; j += 32)
                r[j] = (r[j] - mu) * rin * lnw[j] + lnb[j];
        }
    }
    __syncthreads();

    // GEMM2: da = dt @ W1[H:2H]  (packed f32x2)
    u64 cA[4], cB[4];
    {
        u64 z = pk2(0.f, 0.f);
        #pragma unroll
        for (int i = 0; i < 4; i++) { cA[i] = z; cB[i] = z; }
    }
    for (int j4 = 0; j4 < Hc / 4; j4++) {
        float4 x0 = *(const float4*)&dt[ds][j4 * 4];
        float4 x1 = *(const float4*)&dt[ds + 4][j4 * 4];
        float4 x2 = *(const float4*)&dt[ds + 8][j4 * 4];
        float4 x3 = *(const float4*)&dt[ds + 12][j4 * 4];
        float xv[4][4] = {{x0.x, x0.y, x0.z, x0.w}, {x1.x, x1.y, x1.z, x1.w},
                          {x2.x, x2.y, x2.z, x2.w}, {x3.x, x3.y, x3.z, x3.w}};
        #pragma unroll
        for (int u = 0; u < 4; u++) {
            float4 w = *(const float4*)&W1[(size_t)(Hc + j4 * 4 + u) * Hc + h4];
            u64 wA = pk2(w.x, w.y), wB = pk2(w.z, w.w);
            #pragma unroll
            for (int i = 0; i < 4; i++) {
                u64 xx = pk2(xv[i][u], xv[i][u]);
                fma2(cA[i], wA, xx);
                fma2(cB[i], wB, xx);
            }
        }
    }
    #pragma unroll
    for (int i = 0; i < 4; i++) {
        float2 pA = up2(cA[i]), pB = up2(cB[i]);
        ((float4*)&g_da[(size_t)(docBase + ds + 4 * i) * Hc])[hg] =
            make_float4(pA.x, pA.y, pB.x, pB.y);
    }
}

// ---------------------------------------------------------------------------
// Kernel 3: pairwise scoring.  grid = N/SDOCS, block = 256.
// d-outer / b-inner: dv hoisted once per doc, 4 independent accumulator
// chains per warp for ILP through erff.
// ---------------------------------------------------------------------------
__global__ __launch_bounds__(256) void score_kernel(
    const float* __restrict__ W2, const float* __restrict__ b2,
    const float* __restrict__ temp, int N)
{
    __shared__ float qbs[BMAX * Hc];   // 32 KB
    __shared__ float das[SDOCS][Hc];   // 8 KB
    __shared__ float w2s[Hc];
    int t = threadIdx.x;

    const float4* qsrc = (const float4*)g_qb;
    float4* qdst = (float4*)qbs;
    #pragma unroll
    for (int i = t; i < BMAX * Hc / 4; i += 256) qdst[i] = qsrc[i];
    w2s[t] = W2[t];
    int docBase = blockIdx.x * SDOCS;
    {
        const float4* dsrc = (const float4*)(g_da + (size_t)docBase * Hc);
        float4* ddst = (float4*)&das[0][0];
        ddst[t] = dsrc[t];
        ddst[t + 256] = dsrc[t + 256];
    }
    __syncthreads();

    float invt = 1.0f / (fabsf(temp[0]) + 1e-8f);
    float bb = b2[0];
    int w = t >> 5, lane = t & 31;

    float wv[8];
    #pragma unroll
    for (int j = 0; j < 8; j++) wv[j] = w2s[lane + 32 * j];

    float qv[4][8];
    #pragma unroll
    for (int bi = 0; bi < 4; bi++) {
        const float* qrow = &qbs[(w + 8 * bi) * Hc];
        #pragma unroll
        for (int j = 0; j < 8; j++) qv[bi][j] = qrow[lane + 32 * j];
    }

    #pragma unroll
    for (int d = 0; d < SDOCS; d++) {
        float dv[8];
        #pragma unroll
        for (int j = 0; j < 8; j++) dv[j] = das[d][lane + 32 * j];
        float acc0 = 0.f, acc1 = 0.f, acc2 = 0.f, acc3 = 0.f;
        #pragma unroll
        for (int j = 0; j < 8; j++) {
            float wj = wv[j], dj = dv[j];
            acc0 = fmaf(gelu_f(qv[0][j] + dj), wj, acc0);
            acc1 = fmaf(gelu_f(qv[1][j] + dj), wj, acc1);
            acc2 = fmaf(gelu_f(qv[2][j] + dj), wj, acc2);
            acc3 = fmaf(gelu_f(qv[3][j] + dj), wj, acc3);
        }
        #pragma unroll
        for (int o = 16; o; o >>= 1) {
            acc0 += __shfl_down_sync(0xffffffffu, acc0, o);
            acc1 += __shfl_down_sync(0xffffffffu, acc1, o);
            acc2 += __shfl_down_sync(0xffffffffu, acc2, o);
            acc3 += __shfl_down_sync(0xffffffffu, acc3, o);
        }
        if (lane == 0) {
            g_scores[(size_t)(w +  0) * N + docBase + d] = (acc0 + bb) * invt;
            g_scores[(size_t)(w +  8) * N + docBase + d] = (acc1 + bb) * invt;
            g_scores[(size_t)(w + 16) * N + docBase + d] = (acc2 + bb) * invt;
            g_scores[(size_t)(w + 24) * N + docBase + d] = (acc3 + bb) * invt;
        }
    }
}

// ---------------------------------------------------------------------------
// Top-k keys: (score, index) packed into one orderable uint64.
// Tie-break: equal score -> smaller index (low word = ~index).
// ---------------------------------------------------------------------------
__device__ __forceinline__ unsigned long long pack_key(float s, int i) {
    unsigned int u = __float_as_uint(s);
    u = (u & 0x80000000u) ? ~u : (u | 0x80000000u);
    return ((unsigned long long)u << 32) | (unsigned int)(~(unsigned int)i);
}

// ---------------------------------------------------------------------------
// Kernel 4a: per-warp top-8 over a segment slice.  grid = (SEG, B), block=128.
// Each warp keeps sorted top-8 in registers, then 8 rounds of pure-shuffle
// argmax (no block barriers).  Output: 4 warps x 8 keys per (seg, b).
// ---------------------------------------------------------------------------
__global__ __launch_bounds__(128) void topk_stage1(int N)
{
    int seg = blockIdx.x, b = blockIdx.y, t = threadIdx.x;
    int nseg = gridDim.x;
    int seglen = (N + nseg - 1) / nseg;
    int start = seg * seglen;
    int end = start + seglen; if (end > N) end = N;

    unsigned long long loc[KMAX];
    #pragma unroll
    for (int j = 0; j < KMAX; j++) loc[j] = 0ull;

    const float* row = g_scores + (size_t)b * N;
    for (int i = start + t; i < end; i += 128) {
        unsigned long long key = pack_key(row[i], i);
        if (key > loc[KMAX - 1]) {
            #pragma unroll
            for (int j = 0; j < KMAX; j++) {
                unsigned long long cur = loc[j];
                bool gt = key > cur;
                loc[j] = gt ? key : cur;
                key    = gt ? cur : key;
            }
        }
    }

    int wid = t >> 5, lane = t & 31;
    unsigned long long* outp = &g_part[((b * SEG + seg) * 4 + wid) * KMAX];
    #pragma unroll
    for (int r = 0; r < KMAX; r++) {
        unsigned long long m = loc[0];
        #pragma unroll
        for (int o = 16; o; o >>= 1) {
            unsigned long long v = __shfl_xor_sync(0xffffffffu, m, o);
            m = (v > m) ? v : m;
        }
        if (lane == 0) outp[r] = m;
        if (loc[0] == m) {
            #pragma unroll
            for (int j = 0; j < KMAX - 1; j++) loc[j] = loc[j + 1];
            loc[KMAX - 1] = 0ull;
        }
    }
}

// ---------------------------------------------------------------------------
// Kernel 4b: merge SEG*4*8 = 256 candidates, softmax, write output. grid = B.
// ---------------------------------------------------------------------------
__global__ __launch_bounds__(256) void topk_stage2(
    const int* __restrict__ kptr, float* __restrict__ out, int N, int B)
{
    __shared__ unsigned long long warpmax[8];
    __shared__ unsigned long long bestsh;

    int b = blockIdx.x, t = threadIdx.x;
    int k = *kptr; if (k > KMAX) k = KMAX; if (k < 1) k = 1;

    unsigned long long my = g_part[b * (SEG * 4 * KMAX) + t];

    unsigned long long keys[KMAX];
    int wlane = t & 31, wid = t >> 5;
    for (int r = 0; r < k; r++) {
        unsigned long long m = my;
        #pragma unroll
        for (int o = 16; o; o >>= 1) {
            unsigned long long v = __shfl_xor_sync(0xffffffffu, m, o);
            m = (v > m) ? v : m;
        }
        if (wlane == 0) warpmax[wid] = m;
        __syncthreads();
        if (t == 0) {
            unsigned long long best = 0ull;
            #pragma unroll
            for (int ww = 0; ww < 8; ww++)
                best = (warpmax[ww] > best) ? warpmax[ww] : best;
            bestsh = best;
        }
        __syncthreads();
        unsigned long long best = bestsh;
        if (t == 0) keys[r] = best;
        if (my == best) my = 0ull;
        __syncthreads();
    }

    if (t == 0) {
        float gv[KMAX]; int gi[KMAX];
        for (int r = 0; r < k; r++) {
            unsigned int hi = (unsigned int)(keys[r] >> 32);
            unsigned int u = (hi & 0x80000000u) ? (hi ^ 0x80000000u) : ~hi;
            gv[r] = __uint_as_float(u);
            gi[r] = (int)(~(unsigned int)(keys[r] & 0xffffffffu));
        }
        float mx = gv[0], sum = 0.f, ex[KMAX];
        for (int j = 0; j < k; j++) { ex[j] = expf(gv[j] - mx); sum += ex[j]; }
        float inv = 1.0f / sum;
        for (int j = 0; j < k; j++) {
            out[b * k + j] = (float)gi[j];            // top_idx (as float)
            out[B * k + b * k + j] = ex[j] * inv;     // probs
        }
    }
}

// ---------------------------------------------------------------------------
extern "C" void kernel_launch(void* const* d_in, const int* in_sizes, int n_in,
                              void* d_out, int out_size)
{
    const float* query = (const float*)d_in[0];
    const float* docs  = (const float*)d_in[1];
    const int*   kptr  = (const int*)d_in[2];
    const float* Wq    = (const float*)d_in[3];
    const float* bq    = (const float*)d_in[4];
    const float* lnqw  = (const float*)d_in[5];
    const float* lnqb  = (const float*)d_in[6];
    const float* Wd    = (const float*)d_in[7];
    const float* bd    = (const float*)d_in[8];
    const float* lndw  = (const float*)d_in[9];
    const float* lndb  = (const float*)d_in[10];
    const float* W1    = (const float*)d_in[11];
    const float* b1    = (const float*)d_in[12];
    const float* W2    = (const float*)d_in[13];
    const float* b2    = (const float*)d_in[14];
    const float* temp  = (const float*)d_in[15];

    int H = in_sizes[4];            // 256
    int Z = in_sizes[3] / H;        // 512
    int B = in_sizes[0] / Z;        // 32
    int N = in_sizes[1] / Z;        // 20000

    query_kernel<<<B, 256>>>(query, Wq, bq, lnqw, lnqb, W1, b1);
    doc_kernel<<<(N + DPB - 1) / DPB, 256>>>(docs, Wd, bd, lndw, lndb, W1, N);
    score_kernel<<<N / SDOCS, 256>>>(W2, b2, temp, N);
    dim3 g1(SEG, B);
    topk_stage1<<<g1, 128>>>(N);
    topk_stage2<<<B, 256>>>(kptr, (float*)d_out, N, B);
}

// round 7
// speedup vs baseline: 1.3668x; 1.0939x over previous
#include <cuda_runtime.h>
#include <math.h>

// Problem constants (fixed shapes for this problem instance)
#define Zc 512
#define Hc 256
#define NMAX 20000
#define BMAX 32
#define DPB 16     // docs per block in doc kernel (4 per thread)
#define SDOCS 8    // docs per block in score kernel
#define KMAX 8     // final output k bound
#define K1 16      // per-warp candidate depth in stage1
#define SEG 8      // stage-1 segments per query (x4 warps = 32 slices)
#define NCAND (SEG * 4 * K1)   // 512 candidates per query

// Scratch (no allocations allowed anywhere)
__device__ float g_qb[BMAX * Hc];                 // qa + b1, [B,H]
__device__ float g_da[(size_t)NMAX * Hc];         // d_t @ W1[H:], [N,H]
__device__ float g_scores[(size_t)BMAX * NMAX];   // APPROX scaled scores [B,N]
__device__ unsigned long long g_part[BMAX * NCAND]; // stage-1 candidate keys

typedef unsigned long long u64;

__device__ __forceinline__ u64 pk2(float a, float b) {
    u64 r; asm("mov.b64 %0, {%1,%2};" : "=l"(r) : "f"(a), "f"(b)); return r;
}
__device__ __forceinline__ void fma2(u64 &d, u64 a, u64 b) {
    asm("fma.rn.f32x2 %0, %1, %2, %0;" : "+l"(d) : "l"(a), "l"(b));
}
__device__ __forceinline__ float2 up2(u64 v) {
    float lo, hi; asm("mov.b64 {%0,%1}, %2;" : "=f"(lo), "=f"(hi) : "l"(v));
    return make_float2(lo, hi);
}

__device__ __forceinline__ float gelu_f(float x) {
    // exact gelu: 0.5*x*(1+erf(x/sqrt(2)))
    return 0.5f * x * (1.0f + erff(x * 0.70710678118654752440f));
}

// fast approximate gelu (tanh formulation, hardware tanh.approx) — used ONLY
// for the candidate-scoring pass; winners are re-scored exactly.
__device__ __forceinline__ float gelu_a(float x) {
    float x2 = x * x;
    float inner = x * fmaf(0.035677408136f, x2, 0.7978845608028654f);
    float th;
    asm("tanh.approx.f32 %0, %1;" : "=f"(th) : "f"(inner));
    return 0.5f * x * (1.0f + th);
}

// ---------------------------------------------------------------------------
// Kernel 1: query path.  grid = B, block = 256 (one thread per h)
// ---------------------------------------------------------------------------
__global__ __launch_bounds__(256) void query_kernel(
    const float* __restrict__ q, const float* __restrict__ Wq,
    const float* __restrict__ bq, const float* __restrict__ lnw,
    const float* __restrict__ lnb, const float* __restrict__ W1,
    const float* __restrict__ b1)
{
    __shared__ float xq[Zc];
    __shared__ float qt[Hc];
    __shared__ float red[18];
    int b = blockIdx.x, t = threadIdx.x;
    const float* row = q + (size_t)b * Zc;
    for (int i = t; i < Zc; i += 256) xq[i] = row[i];
    __syncthreads();

    float acc = bq[t];
    #pragma unroll 8
    for (int z = 0; z < Zc; z++) acc = fmaf(xq[z], Wq[z * Hc + t], acc);
    float g = gelu_f(acc);

    float s = g, s2 = g * g;
    #pragma unroll
    for (int o = 16; o; o >>= 1) {
        s  += __shfl_down_sync(0xffffffffu, s, o);
        s2 += __shfl_down_sync(0xffffffffu, s2, o);
    }
    if ((t & 31) == 0) { red[t >> 5] = s; red[8 + (t >> 5)] = s2; }
    __syncthreads();
    if (t == 0) {
        float S = 0.f, S2 = 0.f;
        for (int w = 0; w < 8; w++) { S += red[w]; S2 += red[8 + w]; }
        float mu = S / (float)Hc;
        red[16] = mu;
        red[17] = S2 / (float)Hc - mu * mu;
    }
    __syncthreads();
    float mu = red[16], var = red[17];
    float v = (g - mu) * rsqrtf(var + 1e-5f) * lnw[t] + lnb[t];
    qt[t] = v;
    __syncthreads();

    float a2 = b1[t];  // fold b1 here
    #pragma unroll 8
    for (int j = 0; j < Hc; j++) a2 = fmaf(qt[j], W1[j * Hc + t], a2);
    g_qb[b * Hc + t] = a2;
}

// ---------------------------------------------------------------------------
// Kernel 2: doc path, fused. grid = N/DPB, block = 256.  (unchanged from the
// 433us run: R2 structure + packed fma.rn.f32x2 GEMM inner loops.)
// ---------------------------------------------------------------------------
__global__ __launch_bounds__(256) void doc_kernel(
    const float* __restrict__ docs, const float* __restrict__ Wd,
    const float* __restrict__ bd, const float* __restrict__ lnw,
    const float* __restrict__ lnb, const float* __restrict__ W1, int N)
{
    __shared__ float xs[DPB][Zc];   // 32 KB: raw doc rows
    __shared__ float dt[DPB][Hc];   // 16 KB: activations
    int t = threadIdx.x;
    int hg = t & 63, ds = t >> 6;
    int h4 = hg * 4;
    int docBase = blockIdx.x * DPB;

    const float4* src = (const float4*)(docs + (size_t)docBase * Zc);
    float4* dstp = (float4*)&xs[0][0];
    #pragma unroll
    for (int i = t; i < DPB * Zc / 4; i += 256) dstp[i] = src[i];
    __syncthreads();

    // GEMM1: d = x @ Wd + bd  (each thread: 4h x 4docs, packed f32x2 over h)
    float4 bd4 = *(const float4*)&bd[h4];
    u64 aA[4], aB[4];
    {
        u64 bdA = pk2(bd4.x, bd4.y), bdB = pk2(bd4.z, bd4.w);
        #pragma unroll
        for (int i = 0; i < 4; i++) { aA[i] = bdA; aB[i] = bdB; }
    }
    for (int z4 = 0; z4 < Zc / 4; z4++) {
        float4 x0 = *(const float4*)&xs[ds][z4 * 4];
        float4 x1 = *(const float4*)&xs[ds + 4][z4 * 4];
        float4 x2 = *(const float4*)&xs[ds + 8][z4 * 4];
        float4 x3 = *(const float4*)&xs[ds + 12][z4 * 4];
        float xv[4][4] = {{x0.x, x0.y, x0.z, x0.w}, {x1.x, x1.y, x1.z, x1.w},
                          {x2.x, x2.y, x2.z, x2.w}, {x3.x, x3.y, x3.z, x3.w}};
        #pragma unroll
        for (int u = 0; u < 4; u++) {
            float4 w = *(const float4*)&Wd[(size_t)(z4 * 4 + u) * Hc + h4];
            u64 wA = pk2(w.x, w.y), wB = pk2(w.z, w.w);
            #pragma unroll
            for (int i = 0; i < 4; i++) {
                u64 xx = pk2(xv[i][u], xv[i][u]);
                fma2(aA[i], wA, xx);
                fma2(aB[i], wB, xx);
            }
        }
    }
    #pragma unroll
    for (int i = 0; i < 4; i++) {
        float2 pA = up2(aA[i]), pB = up2(aB[i]);
        dt[ds + 4 * i][h4 + 0] = gelu_f(pA.x);
        dt[ds + 4 * i][h4 + 1] = gelu_f(pA.y);
        dt[ds + 4 * i][h4 + 2] = gelu_f(pB.x);
        dt[ds + 4 * i][h4 + 3] = gelu_f(pB.y);
    }
    __syncthreads();

    // LayerNorm per doc: warp w normalizes docs 2w, 2w+1
    {
        int wid = t >> 5, lane = t & 31;
        #pragma unroll
        for (int dd = 0; dd < 2; dd++) {
            float* r = dt[wid * 2 + dd];
            float s = 0.f, s2 = 0.f;
            #pragma unroll
            for (int j = lane; j < Hc; j += 32) { float v = r[j]; s += v; s2 += v * v; }
            #pragma unroll
            for (int o = 16; o; o >>= 1) {
                s  += __shfl_xor_sync(0xffffffffu, s, o);
                s2 += __shfl_xor_sync(0xffffffffu, s2, o);
            }
            float mu = s / (float)Hc;
            float rin = rsqrtf(s2 / (float)Hc - mu * mu + 1e-5f);
            #pragma unroll
            for (int j = lane; j < Hc; j += 32)
                r[j] = (r[j] - mu) * rin * lnw[j] + lnb[j];
        }
    }
    __syncthreads();

    // GEMM2: da = dt @ W1[H:2H]  (packed f32x2)
    u64 cA[4], cB[4];
    {
        u64 z = pk2(0.f, 0.f);
        #pragma unroll
        for (int i = 0; i < 4; i++) { cA[i] = z; cB[i] = z; }
    }
    for (int j4 = 0; j4 < Hc / 4; j4++) {
        float4 x0 = *(const float4*)&dt[ds][j4 * 4];
        float4 x1 = *(const float4*)&dt[ds + 4][j4 * 4];
        float4 x2 = *(const float4*)&dt[ds + 8][j4 * 4];
        float4 x3 = *(const float4*)&dt[ds + 12][j4 * 4];
        float xv[4][4] = {{x0.x, x0.y, x0.z, x0.w}, {x1.x, x1.y, x1.z, x1.w},
                          {x2.x, x2.y, x2.z, x2.w}, {x3.x, x3.y, x3.z, x3.w}};
        #pragma unroll
        for (int u = 0; u < 4; u++) {
            float4 w = *(const float4*)&W1[(size_t)(Hc + j4 * 4 + u) * Hc + h4];
            u64 wA = pk2(w.x, w.y), wB = pk2(w.z, w.w);
            #pragma unroll
            for (int i = 0; i < 4; i++) {
                u64 xx = pk2(xv[i][u], xv[i][u]);
                fma2(cA[i], wA, xx);
                fma2(cB[i], wB, xx);
            }
        }
    }
    #pragma unroll
    for (int i = 0; i < 4; i++) {
        float2 pA = up2(cA[i]), pB = up2(cB[i]);
        ((float4*)&g_da[(size_t)(docBase + ds + 4 * i) * Hc])[hg] =
            make_float4(pA.x, pA.y, pB.x, pB.y);
    }
}

// ---------------------------------------------------------------------------
// Kernel 3: APPROXIMATE pairwise scoring.  grid = N/SDOCS, block = 256.
// Same structure as before, but gelu via hardware tanh.approx (cheap).
// Winners get re-scored exactly in the rerank kernel.
// ---------------------------------------------------------------------------
__global__ __launch_bounds__(256) void score_kernel(
    const float* __restrict__ W2, const float* __restrict__ b2,
    const float* __restrict__ temp, int N)
{
    __shared__ float qbs[BMAX * Hc];   // 32 KB
    __shared__ float das[SDOCS][Hc];   // 8 KB
    __shared__ float w2s[Hc];
    int t = threadIdx.x;

    const float4* qsrc = (const float4*)g_qb;
    float4* qdst = (float4*)qbs;
    #pragma unroll
    for (int i = t; i < BMAX * Hc / 4; i += 256) qdst[i] = qsrc[i];
    w2s[t] = W2[t];
    int docBase = blockIdx.x * SDOCS;
    {
        const float4* dsrc = (const float4*)(g_da + (size_t)docBase * Hc);
        float4* ddst = (float4*)&das[0][0];
        ddst[t] = dsrc[t];
        ddst[t + 256] = dsrc[t + 256];
    }
    __syncthreads();

    float invt = 1.0f / (fabsf(temp[0]) + 1e-8f);
    float bb = b2[0];
    int w = t >> 5, lane = t & 31;

    float wv[8];
    #pragma unroll
    for (int j = 0; j < 8; j++) wv[j] = w2s[lane + 32 * j];

    float qv[4][8];
    #pragma unroll
    for (int bi = 0; bi < 4; bi++) {
        const float* qrow = &qbs[(w + 8 * bi) * Hc];
        #pragma unroll
        for (int j = 0; j < 8; j++) qv[bi][j] = qrow[lane + 32 * j];
    }

    #pragma unroll
    for (int d = 0; d < SDOCS; d++) {
        float dv[8];
        #pragma unroll
        for (int j = 0; j < 8; j++) dv[j] = das[d][lane + 32 * j];
        float acc0 = 0.f, acc1 = 0.f, acc2 = 0.f, acc3 = 0.f;
        #pragma unroll
        for (int j = 0; j < 8; j++) {
            float wj = wv[j], dj = dv[j];
            acc0 = fmaf(gelu_a(qv[0][j] + dj), wj, acc0);
            acc1 = fmaf(gelu_a(qv[1][j] + dj), wj, acc1);
            acc2 = fmaf(gelu_a(qv[2][j] + dj), wj, acc2);
            acc3 = fmaf(gelu_a(qv[3][j] + dj), wj, acc3);
        }
        #pragma unroll
        for (int o = 16; o; o >>= 1) {
            acc0 += __shfl_down_sync(0xffffffffu, acc0, o);
            acc1 += __shfl_down_sync(0xffffffffu, acc1, o);
            acc2 += __shfl_down_sync(0xffffffffu, acc2, o);
            acc3 += __shfl_down_sync(0xffffffffu, acc3, o);
        }
        if (lane == 0) {
            g_scores[(size_t)(w +  0) * N + docBase + d] = (acc0 + bb) * invt;
            g_scores[(size_t)(w +  8) * N + docBase + d] = (acc1 + bb) * invt;
            g_scores[(size_t)(w + 16) * N + docBase + d] = (acc2 + bb) * invt;
            g_scores[(size_t)(w + 24) * N + docBase + d] = (acc3 + bb) * invt;
        }
    }
}

// ---------------------------------------------------------------------------
// Top-k keys: (score, index) packed into one orderable uint64.
// Tie-break: equal score -> smaller index (low word = ~index).
// ---------------------------------------------------------------------------
__device__ __forceinline__ unsigned long long pack_key(float s, int i) {
    unsigned int u = __float_as_uint(s);
    u = (u & 0x80000000u) ? ~u : (u | 0x80000000u);
    return ((unsigned long long)u << 32) | (unsigned int)(~(unsigned int)i);
}

// ---------------------------------------------------------------------------
// Kernel 4a: per-warp top-16 candidates (approx scores). grid=(SEG,B), b=128.
// Pure shuffle argmax, no block barriers.  32 slices x 16 = 512 cands/query.
// ---------------------------------------------------------------------------
__global__ __launch_bounds__(128) void topk_stage1(int N)
{
    int seg = blockIdx.x, b = blockIdx.y, t = threadIdx.x;
    int nseg = gridDim.x;
    int seglen = (N + nseg - 1) / nseg;
    int start = seg * seglen;
    int end = start + seglen; if (end > N) end = N;

    unsigned long long loc[K1];
    #pragma unroll
    for (int j = 0; j < K1; j++) loc[j] = 0ull;

    const float* row = g_scores + (size_t)b * N;
    for (int i = start + t; i < end; i += 128) {
        unsigned long long key = pack_key(row[i], i);
        if (key > loc[K1 - 1]) {
            #pragma unroll
            for (int j = 0; j < K1; j++) {
                unsigned long long cur = loc[j];
                bool gt = key > cur;
                loc[j] = gt ? key : cur;
                key    = gt ? cur : key;
            }
        }
    }

    int wid = t >> 5, lane = t & 31;
    unsigned long long* outp = &g_part[b * NCAND + ((seg * 4 + wid) * K1)];
    #pragma unroll
    for (int r = 0; r < K1; r++) {
        unsigned long long m = loc[0];
        #pragma unroll
        for (int o = 16; o; o >>= 1) {
            unsigned long long v = __shfl_xor_sync(0xffffffffu, m, o);
            m = (v > m) ? v : m;
        }
        if (lane == 0) outp[r] = m;
        if (loc[0] == m) {
            #pragma unroll
            for (int j = 0; j < K1 - 1; j++) loc[j] = loc[j + 1];
            loc[K1 - 1] = 0ull;
        }
    }
}

// ---------------------------------------------------------------------------
// Kernel 4b: EXACT rerank of 512 candidates + top-k + softmax.  grid = B.
// Recomputes candidate scores with the exact erf gelu using the identical
// per-lane accumulation order and shuffle reduction as the old exact kernel,
// so winning scores are bitwise reproduced.
// ---------------------------------------------------------------------------
__global__ __launch_bounds__(256) void rerank_kernel(
    const int* __restrict__ kptr, const float* __restrict__ W2,
    const float* __restrict__ b2, const float* __restrict__ temp,
    float* __restrict__ out, int N, int B)
{
    __shared__ float qbs[Hc];
    __shared__ float w2s[Hc];
    __shared__ unsigned long long skeys[NCAND];   // 4 KB
    __shared__ unsigned long long warpmax[8];
    __shared__ unsigned long long bestsh;

    int b = blockIdx.x, t = threadIdx.x;
    int k = *kptr; if (k > KMAX) k = KMAX; if (k < 1) k = 1;

    qbs[t] = g_qb[b * Hc + t];
    w2s[t] = W2[t];
    __syncthreads();

    float invt = 1.0f / (fabsf(temp[0]) + 1e-8f);
    float bb = b2[0];
    int w = t >> 5, lane = t & 31;

    float wv[8], qv[8];
    #pragma unroll
    for (int j = 0; j < 8; j++) {
        wv[j] = w2s[lane + 32 * j];
        qv[j] = qbs[lane + 32 * j];
    }

    // warp w handles candidates [w*64, w*64+64)
    const unsigned long long* cands = &g_part[b * NCAND];
    for (int i = 0; i < NCAND / 8; i++) {
        int c = w * (NCAND / 8) + i;
        unsigned long long key = cands[c];
        int idx = (int)(~(unsigned int)(key & 0xffffffffu));
        if (idx < 0) idx = 0; if (idx >= N) idx = N - 1;
        const float* drow = g_da + (size_t)idx * Hc;
        float acc = 0.f;
        #pragma unroll
        for (int j = 0; j < 8; j++) {
            float x = qv[j] + drow[lane + 32 * j];
            acc = fmaf(gelu_f(x), wv[j], acc);
        }
        #pragma unroll
        for (int o = 16; o; o >>= 1)
            acc += __shfl_down_sync(0xffffffffu, acc, o);
        if (lane == 0)
            skeys[c] = pack_key((acc + bb) * invt, idx);
    }
    __syncthreads();

    // top-k over 512 exact keys: thread t owns skeys[t], skeys[t+256]
    unsigned long long m0 = skeys[t], m1 = skeys[t + 256];
    unsigned long long keys[KMAX];
    for (int r = 0; r < k; r++) {
        unsigned long long m = (m0 > m1) ? m0 : m1;
        #pragma unroll
        for (int o = 16; o; o >>= 1) {
            unsigned long long v = __shfl_xor_sync(0xffffffffu, m, o);
            m = (v > m) ? v : m;
        }
        if (lane == 0) warpmax[w] = m;
        __syncthreads();
        if (t == 0) {
            unsigned long long best = 0ull;
            #pragma unroll
            for (int ww = 0; ww < 8; ww++)
                best = (warpmax[ww] > best) ? warpmax[ww] : best;
            bestsh = best;
        }
        __syncthreads();
        unsigned long long best = bestsh;
        if (t == 0) keys[r] = best;
        if (m0 == best) m0 = 0ull;
        if (m1 == best) m1 = 0ull;
        __syncthreads();
    }

    if (t == 0) {
        float gv[KMAX]; int gi[KMAX];
        for (int r = 0; r < k; r++) {
            unsigned int hi = (unsigned int)(keys[r] >> 32);
            unsigned int u = (hi & 0x80000000u) ? (hi ^ 0x80000000u) : ~hi;
            gv[r] = __uint_as_float(u);
            gi[r] = (int)(~(unsigned int)(keys[r] & 0xffffffffu));
        }
        float mx = gv[0], sum = 0.f, ex[KMAX];
        for (int j = 0; j < k; j++) { ex[j] = expf(gv[j] - mx); sum += ex[j]; }
        float inv = 1.0f / sum;
        for (int j = 0; j < k; j++) {
            out[b * k + j] = (float)gi[j];            // top_idx (as float)
            out[B * k + b * k + j] = ex[j] * inv;     // probs
        }
    }
}

// ---------------------------------------------------------------------------
extern "C" void kernel_launch(void* const* d_in, const int* in_sizes, int n_in,
                              void* d_out, int out_size)
{
    const float* query = (const float*)d_in[0];
    const float* docs  = (const float*)d_in[1];
    const int*   kptr  = (const int*)d_in[2];
    const float* Wq    = (const float*)d_in[3];
    const float* bq    = (const float*)d_in[4];
    const float* lnqw  = (const float*)d_in[5];
    const float* lnqb  = (const float*)d_in[6];
    const float* Wd    = (const float*)d_in[7];
    const float* bd    = (const float*)d_in[8];
    const float* lndw  = (const float*)d_in[9];
    const float* lndb  = (const float*)d_in[10];
    const float* W1    = (const float*)d_in[11];
    const float* b1    = (const float*)d_in[12];
    const float* W2    = (const float*)d_in[13];
    const float* b2    = (const float*)d_in[14];
    const float* temp  = (const float*)d_in[15];

    int H = in_sizes[4];            // 256
    int Z = in_sizes[3] / H;        // 512
    int B = in_sizes[0] / Z;        // 32
    int N = in_sizes[1] / Z;        // 20000

    query_kernel<<<B, 256>>>(query, Wq, bq, lnqw, lnqb, W1, b1);
    doc_kernel<<<(N + DPB - 1) / DPB, 256>>>(docs, Wd, bd, lndw, lndb, W1, N);
    score_kernel<<<N / SDOCS, 256>>>(W2, b2, temp, N);
    dim3 g1(SEG, B);
    topk_stage1<<<g1, 128>>>(N);
    rerank_kernel<<<B, 256>>>(kptr, W2, b2, temp, (float*)d_out, N, B);
}